// round 1
// baseline (speedup 1.0000x reference)
#include <cuda_runtime.h>
#include <math.h>

#define BATCH 32
#define SEQ   2048
#define DIM   512
#define KCL   64
#define KGH   80
#define NROW  (BATCH*SEQ)

// ---------------- scratch (device globals; no allocation allowed) ------------
__device__ float g_assn[(size_t)NROW*KGH];      // raw logits  [65536,80]  ~21MB
__device__ float g_assn_sm[(size_t)NROW*KCL];   // softmaxed   [65536,64]  ~17MB
__device__ float g_vlad[(size_t)BATCH*KCL*DIM]; // vlad [b][k][d]          ~4MB
__device__ float g_colsum[KGH];
__device__ float g_colsumsq[KGH];
__device__ float g_scale[KGH];
__device__ float g_shift[KGH];
__device__ float g_asum[BATCH*KCL];
__device__ float g_colinv[BATCH*KCL];
__device__ float g_colunit[BATCH*KCL];
__device__ float g_ginv[BATCH];

// ---------------- 0: zero the atomics accumulators ---------------------------
__global__ void zero_kernel() {
    int t = blockIdx.x * blockDim.x + threadIdx.x;
    if (t < KGH) { g_colsum[t] = 0.f; g_colsumsq[t] = 0.f; }
    if (t < BATCH*KCL) g_asum[t] = 0.f;
}

// ---------------- 1: GEMM1 assn = x @ clusters  + column sum/sumsq -----------
// block: 256 threads (16x16). tile: 128 rows x 80 cols, BK=32.
// thread microtile: 8 rows x 5 cols.
__global__ __launch_bounds__(256) void gemm1_kernel(
    const float* __restrict__ x, const float* __restrict__ clusters)
{
    __shared__ float xs[32][129];   // [k][row], padded
    __shared__ float cs[32][KGH];   // [k][col]
    __shared__ float s_sum[KGH];
    __shared__ float s_sq[KGH];

    const int tid = threadIdx.x;
    const int tx = tid & 15, ty = tid >> 4;
    const int row0 = blockIdx.x * 128;

    float acc[8][5];
#pragma unroll
    for (int i = 0; i < 8; i++)
#pragma unroll
        for (int j = 0; j < 5; j++) acc[i][j] = 0.f;

    for (int k0 = 0; k0 < DIM; k0 += 32) {
        // load x tile (128 rows x 32 k) transposed into smem
#pragma unroll
        for (int i = 0; i < 4; i++) {
            int idx = tid + i * 256;           // 0..1023 float4 slots
            int r   = idx >> 3;                // 0..127
            int kc  = (idx & 7) * 4;           // 0..28
            float4 v = *(const float4*)(x + (size_t)(row0 + r) * DIM + k0 + kc);
            xs[kc+0][r] = v.x; xs[kc+1][r] = v.y; xs[kc+2][r] = v.z; xs[kc+3][r] = v.w;
        }
        // load clusters tile (32 k x 80 cols) — contiguous chunk
#pragma unroll
        for (int i = 0; i < 10; i++) {
            int idx = tid + i * 256;           // 0..2559
            ((float*)cs)[idx] = clusters[(size_t)k0 * KGH + idx];
        }
        __syncthreads();
#pragma unroll
        for (int kk = 0; kk < 32; kk++) {
            float a[8], b[5];
#pragma unroll
            for (int i = 0; i < 8; i++) a[i] = xs[kk][ty*8 + i];
#pragma unroll
            for (int j = 0; j < 5; j++) b[j] = cs[kk][tx*5 + j];
#pragma unroll
            for (int i = 0; i < 8; i++)
#pragma unroll
                for (int j = 0; j < 5; j++) acc[i][j] = fmaf(a[i], b[j], acc[i][j]);
        }
        __syncthreads();
    }

    if (tid < KGH) { s_sum[tid] = 0.f; s_sq[tid] = 0.f; }
    __syncthreads();

#pragma unroll
    for (int j = 0; j < 5; j++) {
        float ps = 0.f, pq = 0.f;
        int col = tx*5 + j;
#pragma unroll
        for (int i = 0; i < 8; i++) {
            float v = acc[i][j];
            ps += v; pq += v*v;
            g_assn[(size_t)(row0 + ty*8 + i) * KGH + col] = v;
        }
        atomicAdd(&s_sum[col], ps);
        atomicAdd(&s_sq[col],  pq);
    }
    __syncthreads();
    if (tid < KGH) {
        atomicAdd(&g_colsum[tid],   s_sum[tid]);
        atomicAdd(&g_colsumsq[tid], s_sq[tid]);
    }
}

// ---------------- 2: BN finalize ---------------------------------------------
__global__ void bn_kernel(const float* __restrict__ gamma, const float* __restrict__ beta) {
    int c = threadIdx.x;
    if (c < KGH) {
        float mean = g_colsum[c] * (1.f / NROW);
        float var  = g_colsumsq[c] * (1.f / NROW) - mean * mean;
        float sc   = gamma[c] * rsqrtf(var + 1e-5f);
        g_scale[c] = sc;
        g_shift[c] = beta[c] - mean * sc;
    }
}

// ---------------- 3: BN-affine + softmax (80 -> keep 64) + a_sum -------------
// 1 warp per row, 8 rows per block.
__global__ __launch_bounds__(256) void softmax_kernel() {
    __shared__ float bsum[KCL];
    const int tid = threadIdx.x, lane = tid & 31, w = tid >> 5;
    const int row = blockIdx.x * 8 + w;
    const int b = row / SEQ;    // same for whole block (2048 % 8 == 0)

    if (tid < KCL) bsum[tid] = 0.f;
    __syncthreads();

    const float* arow = g_assn + (size_t)row * KGH;
    float v0 = fmaf(arow[lane],      g_scale[lane],      g_shift[lane]);
    float v1 = fmaf(arow[lane + 32], g_scale[lane + 32], g_shift[lane + 32]);
    float v2 = -INFINITY;
    if (lane < 16) v2 = fmaf(arow[lane + 64], g_scale[lane + 64], g_shift[lane + 64]);

    float m = fmaxf(fmaxf(v0, v1), v2);
#pragma unroll
    for (int o = 16; o; o >>= 1) m = fmaxf(m, __shfl_xor_sync(0xffffffffu, m, o));

    float e0 = expf(v0 - m);
    float e1 = expf(v1 - m);
    float e2 = (lane < 16) ? expf(v2 - m) : 0.f;
    float s = e0 + e1 + e2;
#pragma unroll
    for (int o = 16; o; o >>= 1) s += __shfl_xor_sync(0xffffffffu, s, o);

    float inv = 1.f / s;
    float p0 = e0 * inv, p1 = e1 * inv;
    float* orow = g_assn_sm + (size_t)row * KCL;
    orow[lane]      = p0;
    orow[lane + 32] = p1;

    atomicAdd(&bsum[lane],      p0);
    atomicAdd(&bsum[lane + 32], p1);
    __syncthreads();
    if (tid < KCL) atomicAdd(&g_asum[b * KCL + tid], bsum[tid]);
}

// ---------------- 4: GEMM2 vlad[b][k][d] = sum_n assn[n][k]*x[n][d] - asum*c2 -
// grid (8 dtiles, 32 batches). block 256 (16x16): thread = 4 k x 4 d.
__global__ __launch_bounds__(256) void gemm2_kernel(
    const float* __restrict__ x, const float* __restrict__ c2)
{
    __shared__ float xs[32][64];   // [n][d]
    __shared__ float as[32][64];   // [n][k]

    const int tid = threadIdx.x;
    const int tx = tid & 15, ty = tid >> 4;
    const int b  = blockIdx.y;
    const int d0 = blockIdx.x * 64;

    float acc[4][4];
#pragma unroll
    for (int i = 0; i < 4; i++)
#pragma unroll
        for (int j = 0; j < 4; j++) acc[i][j] = 0.f;

    const float* xb = x + (size_t)b * SEQ * DIM;
    const float* ab = g_assn_sm + (size_t)b * SEQ * KCL;

    for (int n0 = 0; n0 < SEQ; n0 += 32) {
#pragma unroll
        for (int i = 0; i < 2; i++) {
            int idx = tid + i * 256;      // 0..511 float4 slots
            int nn  = idx >> 4;
            int dc  = (idx & 15) * 4;
            *(float4*)&xs[nn][dc] = *(const float4*)(xb + (size_t)(n0 + nn) * DIM + d0 + dc);
            *(float4*)&as[nn][dc] = *(const float4*)(ab + (size_t)(n0 + nn) * KCL + dc);
        }
        __syncthreads();
#pragma unroll
        for (int nn = 0; nn < 32; nn++) {
            float av[4], xv[4];
            *(float4*)av = *(float4*)&as[nn][ty * 4];
            *(float4*)xv = *(float4*)&xs[nn][tx * 4];
#pragma unroll
            for (int jk = 0; jk < 4; jk++)
#pragma unroll
                for (int jd = 0; jd < 4; jd++)
                    acc[jk][jd] = fmaf(av[jk], xv[jd], acc[jk][jd]);
        }
        __syncthreads();
    }

#pragma unroll
    for (int jk = 0; jk < 4; jk++) {
        int k = ty * 4 + jk;
        float asum = g_asum[b * KCL + k];
        int d = d0 + tx * 4;
        float4 o;
        o.x = acc[jk][0] - asum * c2[(size_t)(d + 0) * KCL + k];
        o.y = acc[jk][1] - asum * c2[(size_t)(d + 1) * KCL + k];
        o.z = acc[jk][2] - asum * c2[(size_t)(d + 2) * KCL + k];
        o.w = acc[jk][3] - asum * c2[(size_t)(d + 3) * KCL + k];
        *(float4*)(g_vlad + (size_t)(b * KCL + k) * DIM + d) = o;
    }
}

// ---------------- 5: per-(b,k) column L2 norm --------------------------------
__global__ void colnorm_kernel() {
    const int tid = threadIdx.x, lane = tid & 31, w = tid >> 5;
    const int col = blockIdx.x * 8 + w;       // 0..2047
    const float* p = g_vlad + (size_t)col * DIM;
    float s = 0.f;
#pragma unroll
    for (int j = 0; j < 4; j++) {
        float4 v = *(const float4*)(p + lane * 4 + j * 128);
        s += v.x*v.x + v.y*v.y + v.z*v.z + v.w*v.w;
    }
#pragma unroll
    for (int o = 16; o; o >>= 1) s += __shfl_xor_sync(0xffffffffu, s, o);
    if (lane == 0) {
        float norm = sqrtf(s);
        float inv  = 1.f / fmaxf(norm, 1e-12f);
        g_colinv[col] = inv;
        float u = norm * inv;
        g_colunit[col] = u * u;
    }
}

// ---------------- 6: per-batch global L2 norm --------------------------------
__global__ void gnorm_kernel() {
    __shared__ float sh[KCL];
    const int b = blockIdx.x, t = threadIdx.x;
    sh[t] = g_colunit[b * KCL + t];
    __syncthreads();
    if (t < 32) {
        float s = sh[t] + sh[t + 32];
#pragma unroll
        for (int o = 16; o; o >>= 1) s += __shfl_xor_sync(0xffffffffu, s, o);
        if (t == 0) g_ginv[b] = 1.f / fmaxf(sqrtf(s), 1e-12f);
    }
}

// ---------------- 7: transpose [b][k][d] -> out[b][d*K+k], apply norms -------
__global__ __launch_bounds__(256) void final_kernel(float* __restrict__ out) {
    __shared__ float s[64][65];
    __shared__ float cinv[KCL];
    const int tid = threadIdx.x;
    const int b = blockIdx.y;
    const int d0 = blockIdx.x * 64;

    float gi = g_ginv[b];
    if (tid < KCL) cinv[tid] = g_colinv[b * KCL + tid] * gi;

#pragma unroll
    for (int i = 0; i < 4; i++) {
        int idx = tid + i * 256;          // 0..1023 float4 slots
        int kk = idx >> 4;
        int dc = (idx & 15) * 4;
        float4 v = *(const float4*)(g_vlad + (size_t)(b * KCL + kk) * DIM + d0 + dc);
        s[kk][dc] = v.x; s[kk][dc+1] = v.y; s[kk][dc+2] = v.z; s[kk][dc+3] = v.w;
    }
    __syncthreads();

#pragma unroll
    for (int i = 0; i < 4; i++) {
        int idx = tid + i * 256;
        int dd = idx >> 4;
        int kc = (idx & 15) * 4;
        float4 o;
        o.x = s[kc+0][dd] * cinv[kc+0];
        o.y = s[kc+1][dd] * cinv[kc+1];
        o.z = s[kc+2][dd] * cinv[kc+2];
        o.w = s[kc+3][dd] * cinv[kc+3];
        *(float4*)(out + (size_t)b * DIM * KCL + (size_t)(d0 + dd) * KCL + kc) = o;
    }
}

// ---------------- launch ------------------------------------------------------
extern "C" void kernel_launch(void* const* d_in, const int* in_sizes, int n_in,
                              void* d_out, int out_size) {
    const float* x        = (const float*)d_in[0];
    const float* clusters = (const float*)d_in[1];
    const float* c2       = (const float*)d_in[2];
    const float* gamma    = (const float*)d_in[3];
    const float* beta     = (const float*)d_in[4];
    float* out = (float*)d_out;

    zero_kernel<<<8, 256>>>();
    gemm1_kernel<<<NROW / 128, 256>>>(x, clusters);
    bn_kernel<<<1, 128>>>(gamma, beta);
    softmax_kernel<<<NROW / 8, 256>>>();
    gemm2_kernel<<<dim3(DIM / 64, BATCH), 256>>>(x, c2);
    colnorm_kernel<<<BATCH * KCL / 8, 256>>>();
    gnorm_kernel<<<BATCH, 64>>>();
    final_kernel<<<dim3(DIM / 64, BATCH), 256>>>(out);
}

// round 2
// speedup vs baseline: 1.0514x; 1.0514x over previous
#include <cuda_runtime.h>
#include <math.h>

#define BATCH 32
#define SEQ   2048
#define DIM   512
#define KCL   64
#define KGH   80
#define NROW  (BATCH*SEQ)

// ---------------- scratch (device globals; no allocation allowed) ------------
__device__ float g_assn[(size_t)NROW*KGH];      // raw logits  [65536,80]  ~21MB
__device__ float g_assn_sm[(size_t)NROW*KCL];   // softmaxed   [65536,64]  ~17MB
__device__ float g_vlad[(size_t)BATCH*KCL*DIM]; // vlad [b][k][d]          ~4MB
__device__ float g_colsum[KGH];
__device__ float g_colsumsq[KGH];
__device__ float g_scale[KGH];
__device__ float g_shift[KGH];
__device__ float g_asum[BATCH*KCL];
__device__ float g_colinv[BATCH*KCL];
__device__ float g_colunit[BATCH*KCL];
__device__ float g_ginv[BATCH];

// ---------------- 0: zero the atomics accumulators ---------------------------
__global__ void zero_kernel() {
    int t = blockIdx.x * blockDim.x + threadIdx.x;
    if (t < KGH) { g_colsum[t] = 0.f; g_colsumsq[t] = 0.f; }
    if (t < BATCH*KCL) g_asum[t] = 0.f;
}

// ---------------- 1: GEMM1 assn = x @ clusters  + column sum/sumsq -----------
// block: 256 threads (16x16). tile: 128 rows x 80 cols, BK=32.
// thread microtile: 8 rows x 5 cols.
__global__ __launch_bounds__(256) void gemm1_kernel(
    const float* __restrict__ x, const float* __restrict__ clusters)
{
    __shared__ float xs[32][129];   // [k][row], padded
    __shared__ float cs[32][KGH];   // [k][col]
    __shared__ float s_sum[KGH];
    __shared__ float s_sq[KGH];

    const int tid = threadIdx.x;
    const int tx = tid & 15, ty = tid >> 4;
    const int row0 = blockIdx.x * 128;

    float acc[8][5];
#pragma unroll
    for (int i = 0; i < 8; i++)
#pragma unroll
        for (int j = 0; j < 5; j++) acc[i][j] = 0.f;

    for (int k0 = 0; k0 < DIM; k0 += 32) {
        // load x tile (128 rows x 32 k) transposed into smem
#pragma unroll
        for (int i = 0; i < 4; i++) {
            int idx = tid + i * 256;           // 0..1023 float4 slots
            int r   = idx >> 3;                // 0..127
            int kc  = (idx & 7) * 4;           // 0..28
            float4 v = *(const float4*)(x + (size_t)(row0 + r) * DIM + k0 + kc);
            xs[kc+0][r] = v.x; xs[kc+1][r] = v.y; xs[kc+2][r] = v.z; xs[kc+3][r] = v.w;
        }
        // load clusters tile (32 k x 80 cols) — contiguous chunk
#pragma unroll
        for (int i = 0; i < 10; i++) {
            int idx = tid + i * 256;           // 0..2559
            ((float*)cs)[idx] = clusters[(size_t)k0 * KGH + idx];
        }
        __syncthreads();
#pragma unroll
        for (int kk = 0; kk < 32; kk++) {
            float a[8], b[5];
#pragma unroll
            for (int i = 0; i < 8; i++) a[i] = xs[kk][ty*8 + i];
#pragma unroll
            for (int j = 0; j < 5; j++) b[j] = cs[kk][tx*5 + j];
#pragma unroll
            for (int i = 0; i < 8; i++)
#pragma unroll
                for (int j = 0; j < 5; j++) acc[i][j] = fmaf(a[i], b[j], acc[i][j]);
        }
        __syncthreads();
    }

    if (tid < KGH) { s_sum[tid] = 0.f; s_sq[tid] = 0.f; }
    __syncthreads();

#pragma unroll
    for (int j = 0; j < 5; j++) {
        float ps = 0.f, pq = 0.f;
        int col = tx*5 + j;
#pragma unroll
        for (int i = 0; i < 8; i++) {
            float v = acc[i][j];
            ps += v; pq += v*v;
            g_assn[(size_t)(row0 + ty*8 + i) * KGH + col] = v;
        }
        atomicAdd(&s_sum[col], ps);
        atomicAdd(&s_sq[col],  pq);
    }
    __syncthreads();
    if (tid < KGH) {
        atomicAdd(&g_colsum[tid],   s_sum[tid]);
        atomicAdd(&g_colsumsq[tid], s_sq[tid]);
    }
}

// ---------------- 2: BN finalize ---------------------------------------------
__global__ void bn_kernel(const float* __restrict__ gamma, const float* __restrict__ beta) {
    int c = threadIdx.x;
    if (c < KGH) {
        float mean = g_colsum[c] * (1.f / NROW);
        float var  = g_colsumsq[c] * (1.f / NROW) - mean * mean;
        float sc   = gamma[c] * rsqrtf(var + 1e-5f);
        g_scale[c] = sc;
        g_shift[c] = beta[c] - mean * sc;
    }
}

// ---------------- 3: BN-affine + softmax (80 -> keep 64) + a_sum -------------
// 1 warp per row, 8 rows per block.
__global__ __launch_bounds__(256) void softmax_kernel() {
    __shared__ float bsum[KCL];
    const int tid = threadIdx.x, lane = tid & 31, w = tid >> 5;
    const int row = blockIdx.x * 8 + w;
    const int b = row / SEQ;    // same for whole block (2048 % 8 == 0)

    if (tid < KCL) bsum[tid] = 0.f;
    __syncthreads();

    const float* arow = g_assn + (size_t)row * KGH;
    float v0 = fmaf(arow[lane],      g_scale[lane],      g_shift[lane]);
    float v1 = fmaf(arow[lane + 32], g_scale[lane + 32], g_shift[lane + 32]);
    float v2 = -INFINITY;
    if (lane < 16) v2 = fmaf(arow[lane + 64], g_scale[lane + 64], g_shift[lane + 64]);

    float m = fmaxf(fmaxf(v0, v1), v2);
#pragma unroll
    for (int o = 16; o; o >>= 1) m = fmaxf(m, __shfl_xor_sync(0xffffffffu, m, o));

    float e0 = expf(v0 - m);
    float e1 = expf(v1 - m);
    float e2 = (lane < 16) ? expf(v2 - m) : 0.f;
    float s = e0 + e1 + e2;
#pragma unroll
    for (int o = 16; o; o >>= 1) s += __shfl_xor_sync(0xffffffffu, s, o);

    float inv = 1.f / s;
    float p0 = e0 * inv, p1 = e1 * inv;
    float* orow = g_assn_sm + (size_t)row * KCL;
    orow[lane]      = p0;
    orow[lane + 32] = p1;

    atomicAdd(&bsum[lane],      p0);
    atomicAdd(&bsum[lane + 32], p1);
    __syncthreads();
    if (tid < KCL) atomicAdd(&g_asum[b * KCL + tid], bsum[tid]);
}

// ---------------- 4: GEMM2 vlad[b][k][d] = sum_n assn[n][k]*x[n][d] - asum*c2 -
// grid (8 dtiles, 32 batches). block 256 (16x16): thread = 4 k x 4 d.
__global__ __launch_bounds__(256) void gemm2_kernel(
    const float* __restrict__ x, const float* __restrict__ c2)
{
    __shared__ float xs[32][64];   // [n][d]
    __shared__ float as[32][64];   // [n][k]

    const int tid = threadIdx.x;
    const int tx = tid & 15, ty = tid >> 4;
    const int b  = blockIdx.y;
    const int d0 = blockIdx.x * 64;

    float acc[4][4];
#pragma unroll
    for (int i = 0; i < 4; i++)
#pragma unroll
        for (int j = 0; j < 4; j++) acc[i][j] = 0.f;

    const float* xb = x + (size_t)b * SEQ * DIM;
    const float* ab = g_assn_sm + (size_t)b * SEQ * KCL;

    for (int n0 = 0; n0 < SEQ; n0 += 32) {
#pragma unroll
        for (int i = 0; i < 2; i++) {
            int idx = tid + i * 256;      // 0..511 float4 slots
            int nn  = idx >> 4;
            int dc  = (idx & 15) * 4;
            *(float4*)&xs[nn][dc] = *(const float4*)(xb + (size_t)(n0 + nn) * DIM + d0 + dc);
            *(float4*)&as[nn][dc] = *(const float4*)(ab + (size_t)(n0 + nn) * KCL + dc);
        }
        __syncthreads();
#pragma unroll
        for (int nn = 0; nn < 32; nn++) {
            float av[4], xv[4];
            *(float4*)av = *(float4*)&as[nn][ty * 4];
            *(float4*)xv = *(float4*)&xs[nn][tx * 4];
#pragma unroll
            for (int jk = 0; jk < 4; jk++)
#pragma unroll
                for (int jd = 0; jd < 4; jd++)
                    acc[jk][jd] = fmaf(av[jk], xv[jd], acc[jk][jd]);
        }
        __syncthreads();
    }

#pragma unroll
    for (int jk = 0; jk < 4; jk++) {
        int k = ty * 4 + jk;
        float asum = g_asum[b * KCL + k];
        int d = d0 + tx * 4;
        float4 o;
        o.x = acc[jk][0] - asum * c2[(size_t)(d + 0) * KCL + k];
        o.y = acc[jk][1] - asum * c2[(size_t)(d + 1) * KCL + k];
        o.z = acc[jk][2] - asum * c2[(size_t)(d + 2) * KCL + k];
        o.w = acc[jk][3] - asum * c2[(size_t)(d + 3) * KCL + k];
        *(float4*)(g_vlad + (size_t)(b * KCL + k) * DIM + d) = o;
    }
}

// ---------------- 5: per-(b,k) column L2 norm --------------------------------
__global__ void colnorm_kernel() {
    const int tid = threadIdx.x, lane = tid & 31, w = tid >> 5;
    const int col = blockIdx.x * 8 + w;       // 0..2047
    const float* p = g_vlad + (size_t)col * DIM;
    float s = 0.f;
#pragma unroll
    for (int j = 0; j < 4; j++) {
        float4 v = *(const float4*)(p + lane * 4 + j * 128);
        s += v.x*v.x + v.y*v.y + v.z*v.z + v.w*v.w;
    }
#pragma unroll
    for (int o = 16; o; o >>= 1) s += __shfl_xor_sync(0xffffffffu, s, o);
    if (lane == 0) {
        float norm = sqrtf(s);
        float inv  = 1.f / fmaxf(norm, 1e-12f);
        g_colinv[col] = inv;
        float u = norm * inv;
        g_colunit[col] = u * u;
    }
}

// ---------------- 6: per-batch global L2 norm --------------------------------
__global__ void gnorm_kernel() {
    __shared__ float sh[KCL];
    const int b = blockIdx.x, t = threadIdx.x;
    sh[t] = g_colunit[b * KCL + t];
    __syncthreads();
    if (t < 32) {
        float s = sh[t] + sh[t + 32];
#pragma unroll
        for (int o = 16; o; o >>= 1) s += __shfl_xor_sync(0xffffffffu, s, o);
        if (t == 0) g_ginv[b] = 1.f / fmaxf(sqrtf(s), 1e-12f);
    }
}

// ---------------- 7: transpose [b][k][d] -> out[b][d*K+k], apply norms -------
__global__ __launch_bounds__(256) void final_kernel(float* __restrict__ out) {
    __shared__ float s[64][65];
    __shared__ float cinv[KCL];
    const int tid = threadIdx.x;
    const int b = blockIdx.y;
    const int d0 = blockIdx.x * 64;

    float gi = g_ginv[b];
    if (tid < KCL) cinv[tid] = g_colinv[b * KCL + tid] * gi;

#pragma unroll
    for (int i = 0; i < 4; i++) {
        int idx = tid + i * 256;          // 0..1023 float4 slots
        int kk = idx >> 4;
        int dc = (idx & 15) * 4;
        float4 v = *(const float4*)(g_vlad + (size_t)(b * KCL + kk) * DIM + d0 + dc);
        s[kk][dc] = v.x; s[kk][dc+1] = v.y; s[kk][dc+2] = v.z; s[kk][dc+3] = v.w;
    }
    __syncthreads();

#pragma unroll
    for (int i = 0; i < 4; i++) {
        int idx = tid + i * 256;
        int dd = idx >> 4;
        int kc = (idx & 15) * 4;
        float4 o;
        o.x = s[kc+0][dd] * cinv[kc+0];
        o.y = s[kc+1][dd] * cinv[kc+1];
        o.z = s[kc+2][dd] * cinv[kc+2];
        o.w = s[kc+3][dd] * cinv[kc+3];
        *(float4*)(out + (size_t)b * DIM * KCL + (size_t)(d0 + dd) * KCL + kc) = o;
    }
}

// ---------------- launch ------------------------------------------------------
extern "C" void kernel_launch(void* const* d_in, const int* in_sizes, int n_in,
                              void* d_out, int out_size) {
    const float* x        = (const float*)d_in[0];
    const float* clusters = (const float*)d_in[1];
    const float* c2       = (const float*)d_in[2];
    const float* gamma    = (const float*)d_in[3];
    const float* beta     = (const float*)d_in[4];
    float* out = (float*)d_out;

    zero_kernel<<<8, 256>>>();
    gemm1_kernel<<<NROW / 128, 256>>>(x, clusters);
    bn_kernel<<<1, 128>>>(gamma, beta);
    softmax_kernel<<<NROW / 8, 256>>>();
    gemm2_kernel<<<dim3(DIM / 64, BATCH), 256>>>(x, c2);
    colnorm_kernel<<<BATCH * KCL / 8, 256>>>();
    gnorm_kernel<<<BATCH, 64>>>();
    final_kernel<<<dim3(DIM / 64, BATCH), 256>>>(out);
}